// round 14
// baseline (speedup 1.0000x reference)
#include <cuda_runtime.h>
#include <math.h>
#include <stdint.h>

#define N_NODES  50000
#define N_EDGESC 800000
#define ND       64
#define ED       32
#define MSG      128
#define HID      256
#define N_AGENTS 25000

// ---------------- scratch ----------------
__device__ int          g_eidx[N_EDGESC];
__device__ int          g_cnt;
__device__ float        g_denom[N_AGENTS];
__device__ float        g_aggr[(size_t)N_AGENTS * MSG];
// edge weights: fragment-major tf32 float2 (hi only)
__device__ __align__(16) float2 g_W1f[8 * 20 * 4 * 32];
__device__ __align__(16) float2 g_W2f[4 * 32 * 4 * 32];
// agent weights: fragment-major float4 = (hi_k, hi_k4, lo_k, lo_k4)  [3xTF32]
__device__ __align__(16) float4 g_Wh1q[8 * 16 * 4 * 32];
__device__ __align__(16) float4 g_Wh2q[8 * 32 * 4 * 32];

__device__ __forceinline__ float tf32r(float x) {
    uint32_t u;
    asm("cvt.rna.tf32.f32 %0, %1;" : "=r"(u) : "f"(x));
    return __uint_as_float(u);
}
__device__ __forceinline__ void mma168(float* d, const uint32_t* a, const uint32_t* b) {
    asm volatile(
        "mma.sync.aligned.m16n8k8.row.col.f32.tf32.tf32.f32 "
        "{%0,%1,%2,%3}, {%4,%5,%6,%7}, {%8,%9}, {%0,%1,%2,%3};"
        : "+f"(d[0]), "+f"(d[1]), "+f"(d[2]), "+f"(d[3])
        : "r"(a[0]), "r"(a[1]), "r"(a[2]), "r"(a[3]), "r"(b[0]), "r"(b[1]));
}
__device__ __forceinline__ void red2(float* dst, float x, float y) {
    asm volatile("red.global.add.v2.f32 [%0], {%1,%2};" :: "l"(dst), "f"(x), "f"(y) : "memory");
}

// ---------------- init / compact / prep ----------------
__global__ void k_init() {
    int i = blockIdx.x * blockDim.x + threadIdx.x;
    if (i < N_AGENTS * MSG / 4)
        ((float4*)g_aggr)[i] = make_float4(0.f, 0.f, 0.f, 0.f);
    if (i < N_AGENTS) g_denom[i] = 0.f;
    if (i == 0) g_cnt = 0;
}
__global__ void k_compact(const int* __restrict__ rcv) {
    int e = blockIdx.x * blockDim.x + threadIdx.x;
    if (e < N_EDGESC && rcv[e] < N_AGENTS) {
        int p = atomicAdd(&g_cnt, 1);
        g_eidx[p] = e;
    }
}
__global__ void k_prep(const float* __restrict__ W1, const float* __restrict__ W2,
                       const float* __restrict__ Wh1, const float* __restrict__ Wh2) {
    int i = blockIdx.x * blockDim.x + threadIdx.x;
    if (i < 20480) {                               // W1f
        int lane = i & 31, nt = (i >> 5) & 3, kg = (i >> 7) % 20, wn = i / 2560;
        int qr = lane >> 2, qc = lane & 3;
        int n = 32 * wn + 8 * nt + qr;
        int k0 = 8 * kg + qc;
        g_W1f[i] = make_float2(tf32r(W1[(size_t)k0 * HID + n]),
                               tf32r(W1[(size_t)(k0 + 4) * HID + n]));
    }
    int j = i - 20480;
    if (j >= 0 && j < 16384) {                     // W2f
        int lane = j & 31, nt = (j >> 5) & 3, kg = (j >> 7) & 31, wn = j >> 12;
        int qr = lane >> 2, qc = lane & 3;
        int n = 32 * wn + 8 * nt + qr;
        int k0 = 8 * kg + qc;
        g_W2f[j] = make_float2(tf32r(W2[(size_t)k0 * MSG + n]),
                               tf32r(W2[(size_t)(k0 + 4) * MSG + n]));
    }
    int t = i - 36864;
    if (t >= 0 && t < 16384) {                     // Wh1q hi/lo
        int lane = t & 31, nt = (t >> 5) & 3, kg = (t >> 7) & 15, wn = t >> 11;
        int qr = lane >> 2, qc = lane & 3;
        int n = 32 * wn + 8 * nt + qr;
        int k0 = 8 * kg + qc;
        float w0 = Wh1[(size_t)k0 * HID + n], w1 = Wh1[(size_t)(k0 + 4) * HID + n];
        float h0 = tf32r(w0), h1 = tf32r(w1);
        g_Wh1q[t] = make_float4(h0, h1, tf32r(w0 - h0), tf32r(w1 - h1));
    }
    int u = i - 53248;
    if (u >= 0 && u < 32768) {                     // Wh2q hi/lo
        int lane = u & 31, nt = (u >> 5) & 3, kg = (u >> 7) & 31, wn = u >> 12;
        int qr = lane >> 2, qc = lane & 3;
        int n = 32 * wn + 8 * nt + qr;
        int k0 = 8 * kg + qc;
        float w0 = Wh2[(size_t)k0 * HID + n], w1 = Wh2[(size_t)(k0 + 4) * HID + n];
        float h0 = tf32r(w0), h1 = tf32r(w1);
        g_Wh2q[u] = make_float4(h0, h1, tf32r(w0 - h0), tf32r(w1 - h1));
    }
}

// ---------------- fused edge MLP: 32-edge tiles, 3 CTAs/SM ----------------
#define SA_STR2  84             // pair row stride (float2); 672 B (mod 128 = 32)
#define SH_STR2  132            // 1056 B
#define OFF_AH   0              // union: sA 21504 / sH 33792
#define OFF_EG   33792
#define OFF_S    33920
#define OFF_R    34048
#define OFF_B1   34176          // 256 f
#define OFF_B2   35200          // 128 f
#define OFF_WG   35712          // 128 f
#define OFF_GATE 36224          // 4 x 32 f
#define SMEM_EDGE 36736

__global__ __launch_bounds__(256, 3) void k_edge_mma(
    const float* __restrict__ nf, const float* __restrict__ ef,
    const float* __restrict__ b1, const float* __restrict__ b2,
    const float* __restrict__ wg, const float* __restrict__ bg,
    const int* __restrict__ snd, const int* __restrict__ rcv)
{
    extern __shared__ char smem[];
    float* sAf = (float*)(smem + OFF_AH);
    int*   sEg = (int*)(smem + OFF_EG);
    int*   sS  = (int*)(smem + OFF_S);
    int*   sR  = (int*)(smem + OFF_R);
    float* sB1 = (float*)(smem + OFF_B1);
    float* sB2 = (float*)(smem + OFF_B2);
    float* sWg = (float*)(smem + OFF_WG);
    float* sGate = (float*)(smem + OFF_GATE);

    int cnt = g_cnt;
    int ci0 = blockIdx.x * 32;
    if (ci0 >= cnt) return;
    int nE = min(32, cnt - ci0);

    int tid = threadIdx.x;
    int wid = tid >> 5, lane = tid & 31;
    int qr = lane >> 2, qc = lane & 3;

    if (tid < 32) {
        int e = (tid < nE) ? g_eidx[ci0 + tid] : g_eidx[ci0];
        sEg[tid] = e;
        sS[tid] = snd[e];
        sR[tid] = rcv[e];
    }
    sB1[tid] = __ldg(b1 + tid);
    if (tid < 128) { sB2[tid] = __ldg(b2 + tid); sWg[tid] = __ldg(wg + tid); }
    __syncthreads();

    // gather A tile [nf[s]|nf[r]|ef] into pair layout (32 x 160)
    for (int i = tid; i < 32 * 40; i += 256) {
        int r = i / 40, q = i % 40;
        float4 v;
        int cb;
        if (q < 16)      { v = __ldg((const float4*)(nf + (size_t)sS[r] * ND) + q);         cb = 4 * q; }
        else if (q < 32) { v = __ldg((const float4*)(nf + (size_t)sR[r] * ND) + (q - 16));  cb = 64 + 4 * (q - 16); }
        else             { v = __ldg((const float4*)(ef + (size_t)sEg[r] * ED) + (q - 32)); cb = 128 + 4 * (q - 32); }
        int g = cb >> 3, comp = (cb >> 2) & 1;
        float* p = sAf + r * (2 * SA_STR2) + 8 * g + comp;
        p[0] = tf32r(v.x); p[2] = tf32r(v.y); p[4] = tf32r(v.z); p[6] = tf32r(v.w);
    }
    __syncthreads();

    // ---- GEMM1: 32x256, K=160. Warp grid 1x8: Mw=32, Nw=32 ----
    float acc1[2][4][4];
    #pragma unroll
    for (int mt = 0; mt < 2; mt++)
        #pragma unroll
        for (int nt = 0; nt < 4; nt++)
            #pragma unroll
            for (int j = 0; j < 4; j++) acc1[mt][nt][j] = 0.f;

    {
        const float2* sAp = (const float2*)sAf;
        const float2* wf = g_W1f + (size_t)wid * 2560 + lane;
        float2 bcur[4], bnxt[4];
        #pragma unroll
        for (int nt = 0; nt < 4; nt++) bcur[nt] = __ldg(wf + nt * 32);

        for (int kg = 0; kg < 20; kg++) {
            if (kg + 1 < 20) {
                #pragma unroll
                for (int nt = 0; nt < 4; nt++) bnxt[nt] = __ldg(wf + (kg + 1) * 128 + nt * 32);
            }
            int aslot = 4 * kg + qc;
            uint32_t af[2][4];
            #pragma unroll
            for (int mt = 0; mt < 2; mt++) {
                float2 a0 = sAp[(16 * mt + qr) * SA_STR2 + aslot];
                float2 a1 = sAp[(16 * mt + 8 + qr) * SA_STR2 + aslot];
                af[mt][0] = __float_as_uint(a0.x); af[mt][1] = __float_as_uint(a1.x);
                af[mt][2] = __float_as_uint(a0.y); af[mt][3] = __float_as_uint(a1.y);
            }
            uint32_t bf[4][2];
            #pragma unroll
            for (int nt = 0; nt < 4; nt++) {
                bf[nt][0] = __float_as_uint(bcur[nt].x);
                bf[nt][1] = __float_as_uint(bcur[nt].y);
            }
            #pragma unroll
            for (int mt = 0; mt < 2; mt++)
                #pragma unroll
                for (int nt = 0; nt < 4; nt++)
                    mma168(acc1[mt][nt], af[mt], bf[nt]);
            #pragma unroll
            for (int nt = 0; nt < 4; nt++) bcur[nt] = bnxt[nt];
        }
    }
    __syncthreads();

    // epilogue1: h = tf32(relu(acc + b1)) -> sH pair layout
    int cb1 = 32 * wid;
    float* sHf = sAf;
    #pragma unroll
    for (int mt = 0; mt < 2; mt++) {
        int ra = 16 * mt + qr, rbr = ra + 8;
        #pragma unroll
        for (int nt = 0; nt < 4; nt++) {
            int c0 = cb1 + 8 * nt + 2 * qc;
            float bb0 = sB1[c0], bb1 = sB1[c0 + 1];
            float* d = acc1[mt][nt];
            #pragma unroll
            for (int u = 0; u < 2; u++) {
                int c = c0 + u;
                int g = c >> 3, e = c & 7;
                int idx = 8 * g + 2 * (e & 3) + (e >> 2);
                sHf[ra * (2 * SH_STR2) + idx]  = tf32r(fmaxf(d[u] + (u ? bb1 : bb0), 0.f));
                sHf[rbr * (2 * SH_STR2) + idx] = tf32r(fmaxf(d[2 + u] + (u ? bb1 : bb0), 0.f));
            }
        }
    }
    __syncthreads();

    // ---- GEMM2: 32x128, K=256. Warp grid 2x4: Mw=16, Nw=32 ----
    int wm2 = wid & 1, wn2 = wid >> 1;
    int rb2 = 16 * wm2, cb2 = 32 * wn2;

    float acc2[4][4];
    #pragma unroll
    for (int nt = 0; nt < 4; nt++)
        #pragma unroll
        for (int j = 0; j < 4; j++) acc2[nt][j] = 0.f;

    {
        const float2* sHp = (const float2*)sHf;
        const float2* wf = g_W2f + (size_t)wn2 * 4096 + lane;
        float2 bcur[4], bnxt[4];
        #pragma unroll
        for (int nt = 0; nt < 4; nt++) bcur[nt] = __ldg(wf + nt * 32);

        for (int kg = 0; kg < 32; kg++) {
            if (kg + 1 < 32) {
                #pragma unroll
                for (int nt = 0; nt < 4; nt++) bnxt[nt] = __ldg(wf + (kg + 1) * 128 + nt * 32);
            }
            int aslot = 4 * kg + qc;
            uint32_t af[4];
            {
                float2 a0 = sHp[(rb2 + qr) * SH_STR2 + aslot];
                float2 a1 = sHp[(rb2 + 8 + qr) * SH_STR2 + aslot];
                af[0] = __float_as_uint(a0.x); af[1] = __float_as_uint(a1.x);
                af[2] = __float_as_uint(a0.y); af[3] = __float_as_uint(a1.y);
            }
            uint32_t bf[4][2];
            #pragma unroll
            for (int nt = 0; nt < 4; nt++) {
                bf[nt][0] = __float_as_uint(bcur[nt].x);
                bf[nt][1] = __float_as_uint(bcur[nt].y);
            }
            #pragma unroll
            for (int nt = 0; nt < 4; nt++)
                mma168(acc2[nt], af, bf[nt]);
            #pragma unroll
            for (int nt = 0; nt < 4; nt++) bcur[nt] = bnxt[nt];
        }
    }

    // epilogue2: msg = relu(acc2+b2); gate dot; ex=exp(logit); denom; red scatter
    {
        float gpa = 0.f, gpb = 0.f;
        #pragma unroll
        for (int nt = 0; nt < 4; nt++) {
            int c0 = cb2 + 8 * nt + 2 * qc;
            float bb0 = sB2[c0], bb1 = sB2[c0 + 1];
            float w0 = sWg[c0], w1 = sWg[c0 + 1];
            float* d = acc2[nt];
            d[0] = fmaxf(d[0] + bb0, 0.f);
            d[1] = fmaxf(d[1] + bb1, 0.f);
            d[2] = fmaxf(d[2] + bb0, 0.f);
            d[3] = fmaxf(d[3] + bb1, 0.f);
            gpa += d[0] * w0 + d[1] * w1;
            gpb += d[2] * w0 + d[3] * w1;
        }
        gpa += __shfl_xor_sync(0xffffffffu, gpa, 1);
        gpa += __shfl_xor_sync(0xffffffffu, gpa, 2);
        gpb += __shfl_xor_sync(0xffffffffu, gpb, 1);
        gpb += __shfl_xor_sync(0xffffffffu, gpb, 2);
        if (qc == 0) {
            sGate[wn2 * 32 + rb2 + qr] = gpa;
            sGate[wn2 * 32 + rb2 + 8 + qr] = gpb;
        }
        __syncthreads();
        if (tid < 32 && tid < nE) {
            float lgv = sGate[tid] + sGate[32 + tid] + sGate[64 + tid] + sGate[96 + tid] + __ldg(bg);
            float ex = expf(lgv);
            atomicAdd(&g_denom[sR[tid]], ex);
            sGate[tid] = ex;
        }
        __syncthreads();
        int ra = rb2 + qr, rbr = rb2 + 8 + qr;
        if (ra < nE) {
            float exa = sGate[ra];
            float* base = g_aggr + (size_t)sR[ra] * MSG;
            #pragma unroll
            for (int nt = 0; nt < 4; nt++) {
                int c0 = cb2 + 8 * nt + 2 * qc;
                red2(base + c0, exa * acc2[nt][0], exa * acc2[nt][1]);
            }
        }
        if (rbr < nE) {
            float exb = sGate[rbr];
            float* base = g_aggr + (size_t)sR[rbr] * MSG;
            #pragma unroll
            for (int nt = 0; nt < 4; nt++) {
                int c0 = cb2 + 8 * nt + 2 * qc;
                red2(base + c0, exb * acc2[nt][2], exb * acc2[nt][3]);
            }
        }
    }
}

// ---------------- agent MLP head: 3xTF32, 32-agent tiles, 2 CTAs/SM ----------------
#define SXQ_STR4  68            // X row stride (float4) = 1088 B (mod 128 = 64)
#define SHQ_STR4  132           // H row stride (float4) = 2112 B
#define AOFF_XH   0             // union: sX 34816 / sH 67584
#define AOFF_PART 67584         // 8 x 32 f = 1024
#define AOFF_INV  68608         // 32 f
#define AOFF_BH1  68736         // 256 f
#define AOFF_BH2  69760         // 256 f
#define AOFF_WO   70784         // 256 f
#define SMEM_AGM  71808

__global__ __launch_bounds__(256, 2) void k_agent_mma(
    const float* __restrict__ bh1, const float* __restrict__ bh2,
    const float* __restrict__ Wo,  const float* __restrict__ bo,
    float* __restrict__ out)
{
    extern __shared__ char smem[];
    float* sXf = (float*)(smem + AOFF_XH);
    float* sPart = (float*)(smem + AOFF_PART);
    float* sInv = (float*)(smem + AOFF_INV);
    float* sBH1 = (float*)(smem + AOFF_BH1);
    float* sBH2 = (float*)(smem + AOFF_BH2);
    float* sWo = (float*)(smem + AOFF_WO);

    int a0 = blockIdx.x * 32;
    int tid = threadIdx.x;
    int wid = tid >> 5, lane = tid & 31;
    int qr = lane >> 2, qc = lane & 3;

    if (tid < 32) {
        int a = a0 + tid;
        sInv[tid] = (a < N_AGENTS) ? 1.f / (g_denom[a] + 1e-9f) : 0.f;
    }
    sBH1[tid] = __ldg(bh1 + tid);
    sBH2[tid] = __ldg(bh2 + tid);
    sWo[tid] = __ldg(Wo + tid);
    __syncthreads();

    // load x = aggr * inv -> hi/lo float4 slots (32 x 128)
    for (int i = tid; i < 32 * 32; i += 256) {
        int r = i >> 5, q = i & 31;
        int a = a0 + r;
        float4 v = (a < N_AGENTS) ? *((const float4*)g_aggr + (size_t)a * 32 + q)
                                  : make_float4(0.f, 0.f, 0.f, 0.f);
        float inv = sInv[r];
        float e[4] = {v.x * inv, v.y * inv, v.z * inv, v.w * inv};
        #pragma unroll
        for (int jj = 0; jj < 4; jj++) {
            int c = 4 * q + jj;
            int slot = 4 * (c >> 3) + (c & 3);
            int comp = (c >> 2) & 1;
            float hi = tf32r(e[jj]);
            float* fb = sXf + r * (4 * SXQ_STR4) + 4 * slot;
            fb[comp] = hi;
            fb[2 + comp] = tf32r(e[jj] - hi);
        }
    }
    __syncthreads();

    // GEMM1: h1(32x256) = relu(x(32x128) @ Wh1 + bh1). 1x8 warp grid, 3xTF32.
    float acc1[2][4][4];
    #pragma unroll
    for (int mt = 0; mt < 2; mt++)
        #pragma unroll
        for (int nt = 0; nt < 4; nt++)
            #pragma unroll
            for (int j = 0; j < 4; j++) acc1[mt][nt][j] = 0.f;

    {
        const float4* sXp = (const float4*)sXf;
        const float4* wf = g_Wh1q + (size_t)wid * 2048 + lane;
        float4 bcur[4], bnxt[4];
        #pragma unroll
        for (int nt = 0; nt < 4; nt++) bcur[nt] = __ldg(wf + nt * 32);

        for (int kg = 0; kg < 16; kg++) {
            if (kg + 1 < 16) {
                #pragma unroll
                for (int nt = 0; nt < 4; nt++) bnxt[nt] = __ldg(wf + (kg + 1) * 128 + nt * 32);
            }
            int aslot = 4 * kg + qc;
            uint32_t ah[2][4], al[2][4];
            #pragma unroll
            for (int mt = 0; mt < 2; mt++) {
                float4 a0v = sXp[(16 * mt + qr) * SXQ_STR4 + aslot];
                float4 a1v = sXp[(16 * mt + 8 + qr) * SXQ_STR4 + aslot];
                ah[mt][0] = __float_as_uint(a0v.x); ah[mt][1] = __float_as_uint(a1v.x);
                ah[mt][2] = __float_as_uint(a0v.y); ah[mt][3] = __float_as_uint(a1v.y);
                al[mt][0] = __float_as_uint(a0v.z); al[mt][1] = __float_as_uint(a1v.z);
                al[mt][2] = __float_as_uint(a0v.w); al[mt][3] = __float_as_uint(a1v.w);
            }
            #pragma unroll
            for (int nt = 0; nt < 4; nt++) {
                uint32_t bh[2] = {__float_as_uint(bcur[nt].x), __float_as_uint(bcur[nt].y)};
                uint32_t bl[2] = {__float_as_uint(bcur[nt].z), __float_as_uint(bcur[nt].w)};
                #pragma unroll
                for (int mt = 0; mt < 2; mt++) {
                    mma168(acc1[mt][nt], ah[mt], bh);
                    mma168(acc1[mt][nt], ah[mt], bl);
                    mma168(acc1[mt][nt], al[mt], bh);
                }
            }
            #pragma unroll
            for (int nt = 0; nt < 4; nt++) bcur[nt] = bnxt[nt];
        }
    }
    __syncthreads();

    // epilogue1: h1 = relu(acc + bh1) -> hi/lo float4 slots
    int cb1 = 32 * wid;
    float* sHf = sXf;
    #pragma unroll
    for (int mt = 0; mt < 2; mt++) {
        int ra = 16 * mt + qr, rbr = ra + 8;
        #pragma unroll
        for (int nt = 0; nt < 4; nt++) {
            int c0 = cb1 + 8 * nt + 2 * qc;
            float bb0 = sBH1[c0], bb1 = sBH1[c0 + 1];
            float* d = acc1[mt][nt];
            #pragma unroll
            for (int u = 0; u < 2; u++) {
                int c = c0 + u;
                int slot = 4 * (c >> 3) + (c & 3);
                int comp = (c >> 2) & 1;
                float va = fmaxf(d[u] + (u ? bb1 : bb0), 0.f);
                float vb = fmaxf(d[2 + u] + (u ? bb1 : bb0), 0.f);
                float ha = tf32r(va), hb = tf32r(vb);
                float* fa = sHf + ra * (4 * SHQ_STR4) + 4 * slot;
                float* fb = sHf + rbr * (4 * SHQ_STR4) + 4 * slot;
                fa[comp] = ha; fa[2 + comp] = tf32r(va - ha);
                fb[comp] = hb; fb[2 + comp] = tf32r(vb - hb);
            }
        }
    }
    __syncthreads();

    // GEMM2: h2(32x256) = h1(32x256) @ Wh2. 1x8 warp grid, K=256, 3xTF32.
    float acc2[2][4][4];
    #pragma unroll
    for (int mt = 0; mt < 2; mt++)
        #pragma unroll
        for (int nt = 0; nt < 4; nt++)
            #pragma unroll
            for (int j = 0; j < 4; j++) acc2[mt][nt][j] = 0.f;

    {
        const float4* sHp = (const float4*)sHf;
        const float4* wf = g_Wh2q + (size_t)wid * 4096 + lane;
        float4 bcur[4], bnxt[4];
        #pragma unroll
        for (int nt = 0; nt < 4; nt++) bcur[nt] = __ldg(wf + nt * 32);

        for (int kg = 0; kg < 32; kg++) {
            if (kg + 1 < 32) {
                #pragma unroll
                for (int nt = 0; nt < 4; nt++) bnxt[nt] = __ldg(wf + (kg + 1) * 128 + nt * 32);
            }
            int aslot = 4 * kg + qc;
            uint32_t ah[2][4], al[2][4];
            #pragma unroll
            for (int mt = 0; mt < 2; mt++) {
                float4 a0v = sHp[(16 * mt + qr) * SHQ_STR4 + aslot];
                float4 a1v = sHp[(16 * mt + 8 + qr) * SHQ_STR4 + aslot];
                ah[mt][0] = __float_as_uint(a0v.x); ah[mt][1] = __float_as_uint(a1v.x);
                ah[mt][2] = __float_as_uint(a0v.y); ah[mt][3] = __float_as_uint(a1v.y);
                al[mt][0] = __float_as_uint(a0v.z); al[mt][1] = __float_as_uint(a1v.z);
                al[mt][2] = __float_as_uint(a0v.w); al[mt][3] = __float_as_uint(a1v.w);
            }
            #pragma unroll
            for (int nt = 0; nt < 4; nt++) {
                uint32_t bh[2] = {__float_as_uint(bcur[nt].x), __float_as_uint(bcur[nt].y)};
                uint32_t bl[2] = {__float_as_uint(bcur[nt].z), __float_as_uint(bcur[nt].w)};
                #pragma unroll
                for (int mt = 0; mt < 2; mt++) {
                    mma168(acc2[mt][nt], ah[mt], bh);
                    mma168(acc2[mt][nt], ah[mt], bl);
                    mma168(acc2[mt][nt], al[mt], bh);
                }
            }
            #pragma unroll
            for (int nt = 0; nt < 4; nt++) bcur[nt] = bnxt[nt];
        }
    }

    // final epilogue: h2 = relu(acc2 + bh2); Wo dot partials; reduce; tanh
    {
        float pa[2] = {0.f, 0.f}, pb[2] = {0.f, 0.f};
        #pragma unroll
        for (int mt = 0; mt < 2; mt++) {
            #pragma unroll
            for (int nt = 0; nt < 4; nt++) {
                int c0 = cb1 + 8 * nt + 2 * qc;
                float bb0 = sBH2[c0], bb1 = sBH2[c0 + 1];
                float w0 = sWo[c0], w1 = sWo[c0 + 1];
                float* d = acc2[mt][nt];
                float m0 = fmaxf(d[0] + bb0, 0.f);
                float m1 = fmaxf(d[1] + bb1, 0.f);
                float m2 = fmaxf(d[2] + bb0, 0.f);
                float m3 = fmaxf(d[3] + bb1, 0.f);
                pa[mt] += m0 * w0 + m1 * w1;
                pb[mt] += m2 * w0 + m3 * w1;
            }
        }
        #pragma unroll
        for (int mt = 0; mt < 2; mt++) {
            pa[mt] += __shfl_xor_sync(0xffffffffu, pa[mt], 1);
            pa[mt] += __shfl_xor_sync(0xffffffffu, pa[mt], 2);
            pb[mt] += __shfl_xor_sync(0xffffffffu, pb[mt], 1);
            pb[mt] += __shfl_xor_sync(0xffffffffu, pb[mt], 2);
        }
        if (qc == 0) {
            #pragma unroll
            for (int mt = 0; mt < 2; mt++) {
                sPart[wid * 32 + 16 * mt + qr] = pa[mt];
                sPart[wid * 32 + 16 * mt + 8 + qr] = pb[mt];
            }
        }
        __syncthreads();
        if (tid < 32) {
            int a = a0 + tid;
            if (a < N_AGENTS) {
                float s = __ldg(bo);
                #pragma unroll
                for (int w = 0; w < 8; w++) s += sPart[w * 32 + tid];
                out[a] = tanhf(s);
            }
        }
    }
}

// ---------------- launch ----------------
extern "C" void kernel_launch(void* const* d_in, const int* in_sizes, int n_in,
                              void* d_out, int out_size)
{
    const float* node = (const float*)d_in[0];
    const float* ef   = (const float*)d_in[1];
    const float* W1   = (const float*)d_in[2];
    const float* b1   = (const float*)d_in[3];
    const float* W2   = (const float*)d_in[4];
    const float* b2   = (const float*)d_in[5];
    const float* wg   = (const float*)d_in[6];
    const float* bg   = (const float*)d_in[7];
    const float* Wh1  = (const float*)d_in[8];
    const float* bh1  = (const float*)d_in[9];
    const float* Wh2  = (const float*)d_in[10];
    const float* bh2  = (const float*)d_in[11];
    const float* Wo   = (const float*)d_in[12];
    const float* bo   = (const float*)d_in[13];
    const int*   snd  = (const int*)d_in[14];
    const int*   rcv  = (const int*)d_in[15];
    float* out = (float*)d_out;

    cudaFuncSetAttribute(k_edge_mma,  cudaFuncAttributeMaxDynamicSharedMemorySize, SMEM_EDGE);
    cudaFuncSetAttribute(k_agent_mma, cudaFuncAttributeMaxDynamicSharedMemorySize, SMEM_AGM);

    k_init<<<(N_AGENTS * MSG / 4 + 255) / 256, 256>>>();
    k_compact<<<(N_EDGESC + 255) / 256, 256>>>(rcv);
    k_prep<<<(86016 + 255) / 256, 256>>>(W1, W2, Wh1, Wh2);
    k_edge_mma<<<(N_EDGESC + 31) / 32, 256, SMEM_EDGE>>>(node, ef, b1, b2, wg, bg, snd, rcv);
    k_agent_mma<<<(N_AGENTS + 31) / 32, 256, SMEM_AGM>>>(bh1, bh2, Wo, bo, out);
}

// round 15
// speedup vs baseline: 1.0329x; 1.0329x over previous
#include <cuda_runtime.h>
#include <math.h>
#include <stdint.h>

#define N_NODES  50000
#define N_EDGESC 800000
#define ND       64
#define ED       32
#define MSG      128
#define HID      256
#define N_AGENTS 25000

// ---------------- scratch ----------------
__device__ int          g_eidx[N_EDGESC];
__device__ int          g_cnt;
__device__ float        g_denom[N_AGENTS];
__device__ float        g_aggr[(size_t)N_AGENTS * MSG];
// edge weights: fragment-major tf32 float2 (hi only)
__device__ __align__(16) float2 g_W1f[8 * 20 * 4 * 32];
__device__ __align__(16) float2 g_W2f[4 * 32 * 4 * 32];
// agent weights: fragment-major float4 = (hi_k, hi_k4, lo_k, lo_k4)  [3xTF32]
__device__ __align__(16) float4 g_Wh1q[8 * 16 * 4 * 32];
__device__ __align__(16) float4 g_Wh2q[8 * 32 * 4 * 32];

__device__ __forceinline__ float tf32r(float x) {
    uint32_t u;
    asm("cvt.rna.tf32.f32 %0, %1;" : "=r"(u) : "f"(x));
    return __uint_as_float(u);
}
__device__ __forceinline__ void mma168(float* d, const uint32_t* a, const uint32_t* b) {
    asm volatile(
        "mma.sync.aligned.m16n8k8.row.col.f32.tf32.tf32.f32 "
        "{%0,%1,%2,%3}, {%4,%5,%6,%7}, {%8,%9}, {%0,%1,%2,%3};"
        : "+f"(d[0]), "+f"(d[1]), "+f"(d[2]), "+f"(d[3])
        : "r"(a[0]), "r"(a[1]), "r"(a[2]), "r"(a[3]), "r"(b[0]), "r"(b[1]));
}
__device__ __forceinline__ void red2(float* dst, float x, float y) {
    asm volatile("red.global.add.v2.f32 [%0], {%1,%2};" :: "l"(dst), "f"(x), "f"(y) : "memory");
}

// ---------------- fused setup: init + compact + weight prep in ONE launch ----------------
// grid covers 800000 threads: aggr zero (800000 float4), edge compact (800000),
// denom zero (25000), weight fragments (86016), cnt reset (1).
__global__ void k_setup(const int* __restrict__ rcv,
                        const float* __restrict__ W1, const float* __restrict__ W2,
                        const float* __restrict__ Wh1, const float* __restrict__ Wh2) {
    int i = blockIdx.x * blockDim.x + threadIdx.x;
    if (i == 0) g_cnt = 0;
    if (i < N_AGENTS * MSG / 4)
        ((float4*)g_aggr)[i] = make_float4(0.f, 0.f, 0.f, 0.f);
    if (i < N_AGENTS) g_denom[i] = 0.f;
    // NOTE: g_cnt=0 store above and the atomicAdd below are in the same grid;
    // ordering is guaranteed because thread 0's store and other threads' atomics
    // could race. Avoid by having compact use its own zero epoch: we instead
    // reset cnt via a separate tiny guard: compaction uses atomicAdd on g_cnt
    // which thread 0 reset. To make this safe, thread 0 resets BEFORE any atomic:
    // enforced by doing the reset in k_setup's first block AND gating compaction
    // on a grid-wide ordering hazard. Since CUDA gives no intra-grid ordering,
    // we instead reset g_cnt from the HOST side pattern: g_cnt is reset here but
    // compaction is done in this same kernel only AFTER a device-wide fence is
    // impossible -> so compaction writes positions from atomicAdd on a counter
    // that some thread may not yet see as 0. FIX: use a dedicated counter that
    // k_setup zeroes at the END of the previous graph replay: simplest correct
    // form: compact in this kernel but with the counter reset moved to the
    // consumer side. We sidestep the entire hazard by deriving the slot with
    // atomicAdd on g_cnt initialized by cudaMemsetAsync-like store from the
    // FIRST launched thread of this grid -- but that is exactly the race.
    //
    // Correct resolution used here: g_cnt reset happens in this kernel ONLY via
    // thread 0 of block 0, and compaction atomics are delayed to a second pass
    // inside the same kernel guarded by cooperative ordering we do not have.
    // Therefore: compaction counter uses atomicSub from N_EDGESC sentinel...
    //
    // --- Simplest correct scheme (used below): counter lives in g_cnt, reset by
    // the PREVIOUS kernel in the graph?  There is none.  So we keep compaction
    // here but make the reset unconditional per-thread-safe: every thread uses
    // atomicAdd(&g_cnt,1) AFTER observing a zeroed counter only if reset
    // happened-before.  Since we cannot guarantee that, compaction position is
    // instead computed as atomicAdd on g_cnt where g_cnt is zeroed by
    // __threadfence + spin... overkill.
    //
    // FINAL: compaction slot = atomicAdd(&g_cnt2,1) with g_cnt2 zeroed by k_setup
    // caller via a preceding 1-thread kernel is what we had before.  To keep ONE
    // launch and correctness, we use the sign trick: g_cnt holds (epoch-tagged)
    // value impossible; instead we simply zero g_cnt in a preceding tiny kernel.
    // (See k_zero below -- it is 1 block, overlaps nothing measurable.)
    if (i < N_EDGESC && rcv[i] < N_AGENTS) {
        int p = atomicAdd(&g_cnt, 1);
        g_eidx[p] = i;
    }
    if (i < 20480) {                               // W1f
        int lane = i & 31, nt = (i >> 5) & 3, kg = (i >> 7) % 20, wn = i / 2560;
        int qr = lane >> 2, qc = lane & 3;
        int n = 32 * wn + 8 * nt + qr;
        int k0 = 8 * kg + qc;
        g_W1f[i] = make_float2(tf32r(W1[(size_t)k0 * HID + n]),
                               tf32r(W1[(size_t)(k0 + 4) * HID + n]));
    }
    int j = i - 20480;
    if (j >= 0 && j < 16384) {                     // W2f
        int lane = j & 31, nt = (j >> 5) & 3, kg = (j >> 7) & 31, wn = j >> 12;
        int qr = lane >> 2, qc = lane & 3;
        int n = 32 * wn + 8 * nt + qr;
        int k0 = 8 * kg + qc;
        g_W2f[j] = make_float2(tf32r(W2[(size_t)k0 * MSG + n]),
                               tf32r(W2[(size_t)(k0 + 4) * MSG + n]));
    }
    int t = i - 36864;
    if (t >= 0 && t < 16384) {                     // Wh1q hi/lo
        int lane = t & 31, nt = (t >> 5) & 3, kg = (t >> 7) & 15, wn = t >> 11;
        int qr = lane >> 2, qc = lane & 3;
        int n = 32 * wn + 8 * nt + qr;
        int k0 = 8 * kg + qc;
        float w0 = Wh1[(size_t)k0 * HID + n], w1 = Wh1[(size_t)(k0 + 4) * HID + n];
        float h0 = tf32r(w0), h1 = tf32r(w1);
        g_Wh1q[t] = make_float4(h0, h1, tf32r(w0 - h0), tf32r(w1 - h1));
    }
    int u = i - 53248;
    if (u >= 0 && u < 32768) {                     // Wh2q hi/lo
        int lane = u & 31, nt = (u >> 5) & 3, kg = (u >> 7) & 31, wn = u >> 12;
        int qr = lane >> 2, qc = lane & 3;
        int n = 32 * wn + 8 * nt + qr;
        int k0 = 8 * kg + qc;
        float w0 = Wh2[(size_t)k0 * HID + n], w1 = Wh2[(size_t)(k0 + 4) * HID + n];
        float h0 = tf32r(w0), h1 = tf32r(w1);
        g_Wh2q[u] = make_float4(h0, h1, tf32r(w0 - h0), tf32r(w1 - h1));
    }
}
// tiny counter-reset kernel (must precede k_setup; 1 block, ~launch-overhead only)
__global__ void k_zero() { if (threadIdx.x == 0) g_cnt = 0; }

// ---------------- fused edge MLP + softmax-numerator scatter (round-13 best) ----------------
#define SA_STR2  84
#define SH_STR2  132
#define OFF_AH   0
#define OFF_EG   67584
#define OFF_S    67840
#define OFF_R    68096
#define OFF_B1   68352
#define OFF_B2   69376
#define OFF_WG   69888
#define OFF_GATE 70400
#define SMEM_EDGE 71424

__global__ __launch_bounds__(256, 2) void k_edge_mma(
    const float* __restrict__ nf, const float* __restrict__ ef,
    const float* __restrict__ b1, const float* __restrict__ b2,
    const float* __restrict__ wg, const float* __restrict__ bg,
    const int* __restrict__ snd, const int* __restrict__ rcv)
{
    extern __shared__ char smem[];
    float* sAf = (float*)(smem + OFF_AH);
    int*   sEg = (int*)(smem + OFF_EG);
    int*   sS  = (int*)(smem + OFF_S);
    int*   sR  = (int*)(smem + OFF_R);
    float* sB1 = (float*)(smem + OFF_B1);
    float* sB2 = (float*)(smem + OFF_B2);
    float* sWg = (float*)(smem + OFF_WG);
    float* sGate = (float*)(smem + OFF_GATE);

    int cnt = g_cnt;
    int ci0 = blockIdx.x * 64;
    if (ci0 >= cnt) return;
    int nE = min(64, cnt - ci0);

    int tid = threadIdx.x;
    int wid = tid >> 5, lane = tid & 31;
    int qr = lane >> 2, qc = lane & 3;

    if (tid < 64) {
        int e = (tid < nE) ? g_eidx[ci0 + tid] : g_eidx[ci0];
        sEg[tid] = e;
        sS[tid] = snd[e];
        sR[tid] = rcv[e];
    }
    sB1[tid] = __ldg(b1 + tid);
    if (tid < 128) { sB2[tid] = __ldg(b2 + tid); sWg[tid] = __ldg(wg + tid); }
    __syncthreads();

    for (int i = tid; i < 64 * 40; i += 256) {
        int r = i / 40, q = i % 40;
        float4 v;
        int cb;
        if (q < 16)      { v = __ldg((const float4*)(nf + (size_t)sS[r] * ND) + q);         cb = 4 * q; }
        else if (q < 32) { v = __ldg((const float4*)(nf + (size_t)sR[r] * ND) + (q - 16));  cb = 64 + 4 * (q - 16); }
        else             { v = __ldg((const float4*)(ef + (size_t)sEg[r] * ED) + (q - 32)); cb = 128 + 4 * (q - 32); }
        int g = cb >> 3, comp = (cb >> 2) & 1;
        float* p = sAf + r * (2 * SA_STR2) + 8 * g + comp;
        p[0] = tf32r(v.x); p[2] = tf32r(v.y); p[4] = tf32r(v.z); p[6] = tf32r(v.w);
    }
    __syncthreads();

    // GEMM1: 64x256, K=160
    float acc1[4][4][4];
    #pragma unroll
    for (int mt = 0; mt < 4; mt++)
        #pragma unroll
        for (int nt = 0; nt < 4; nt++)
            #pragma unroll
            for (int j = 0; j < 4; j++) acc1[mt][nt][j] = 0.f;

    {
        const float2* sAp = (const float2*)sAf;
        const float2* wf = g_W1f + (size_t)wid * 2560 + lane;
        float2 bcur[4], bnxt[4];
        #pragma unroll
        for (int nt = 0; nt < 4; nt++) bcur[nt] = __ldg(wf + nt * 32);

        for (int kg = 0; kg < 20; kg++) {
            if (kg + 1 < 20) {
                #pragma unroll
                for (int nt = 0; nt < 4; nt++) bnxt[nt] = __ldg(wf + (kg + 1) * 128 + nt * 32);
            }
            int aslot = 4 * kg + qc;
            uint32_t af[4][4];
            #pragma unroll
            for (int mt = 0; mt < 4; mt++) {
                float2 a0 = sAp[(16 * mt + qr) * SA_STR2 + aslot];
                float2 a1 = sAp[(16 * mt + 8 + qr) * SA_STR2 + aslot];
                af[mt][0] = __float_as_uint(a0.x); af[mt][1] = __float_as_uint(a1.x);
                af[mt][2] = __float_as_uint(a0.y); af[mt][3] = __float_as_uint(a1.y);
            }
            uint32_t bf[4][2];
            #pragma unroll
            for (int nt = 0; nt < 4; nt++) {
                bf[nt][0] = __float_as_uint(bcur[nt].x);
                bf[nt][1] = __float_as_uint(bcur[nt].y);
            }
            #pragma unroll
            for (int mt = 0; mt < 4; mt++)
                #pragma unroll
                for (int nt = 0; nt < 4; nt++)
                    mma168(acc1[mt][nt], af[mt], bf[nt]);
            #pragma unroll
            for (int nt = 0; nt < 4; nt++) bcur[nt] = bnxt[nt];
        }
    }
    __syncthreads();

    // epilogue1
    int cb1 = 32 * wid;
    float* sHf = sAf;
    #pragma unroll
    for (int mt = 0; mt < 4; mt++) {
        int ra = 16 * mt + qr, rbr = ra + 8;
        #pragma unroll
        for (int nt = 0; nt < 4; nt++) {
            int c0 = cb1 + 8 * nt + 2 * qc;
            float bb0 = sB1[c0], bb1 = sB1[c0 + 1];
            float* d = acc1[mt][nt];
            #pragma unroll
            for (int u = 0; u < 2; u++) {
                int c = c0 + u;
                int g = c >> 3, e = c & 7;
                int idx = 8 * g + 2 * (e & 3) + (e >> 2);
                sHf[ra * (2 * SH_STR2) + idx]  = tf32r(fmaxf(d[u] + (u ? bb1 : bb0), 0.f));
                sHf[rbr * (2 * SH_STR2) + idx] = tf32r(fmaxf(d[2 + u] + (u ? bb1 : bb0), 0.f));
            }
        }
    }
    __syncthreads();

    // GEMM2: 64x128, K=256
    int wm2 = wid & 1, wn2 = wid >> 1;
    int rb2 = 32 * wm2, cb2 = 32 * wn2;

    float acc2[2][4][4];
    #pragma unroll
    for (int mt = 0; mt < 2; mt++)
        #pragma unroll
        for (int nt = 0; nt < 4; nt++)
            #pragma unroll
            for (int j = 0; j < 4; j++) acc2[mt][nt][j] = 0.f;

    {
        const float2* sHp = (const float2*)sHf;
        const float2* wf = g_W2f + (size_t)wn2 * 4096 + lane;
        float2 bcur[4], bnxt[4];
        #pragma unroll
        for (int nt = 0; nt < 4; nt++) bcur[nt] = __ldg(wf + nt * 32);

        for (int kg = 0; kg < 32; kg++) {
            if (kg + 1 < 32) {
                #pragma unroll
                for (int nt = 0; nt < 4; nt++) bnxt[nt] = __ldg(wf + (kg + 1) * 128 + nt * 32);
            }
            int aslot = 4 * kg + qc;
            uint32_t af[2][4];
            #pragma unroll
            for (int mt = 0; mt < 2; mt++) {
                float2 a0 = sHp[(rb2 + 16 * mt + qr) * SH_STR2 + aslot];
                float2 a1 = sHp[(rb2 + 16 * mt + 8 + qr) * SH_STR2 + aslot];
                af[mt][0] = __float_as_uint(a0.x); af[mt][1] = __float_as_uint(a1.x);
                af[mt][2] = __float_as_uint(a0.y); af[mt][3] = __float_as_uint(a1.y);
            }
            uint32_t bf[4][2];
            #pragma unroll
            for (int nt = 0; nt < 4; nt++) {
                bf[nt][0] = __float_as_uint(bcur[nt].x);
                bf[nt][1] = __float_as_uint(bcur[nt].y);
            }
            #pragma unroll
            for (int mt = 0; mt < 2; mt++)
                #pragma unroll
                for (int nt = 0; nt < 4; nt++)
                    mma168(acc2[mt][nt], af[mt], bf[nt]);
            #pragma unroll
            for (int nt = 0; nt < 4; nt++) bcur[nt] = bnxt[nt];
        }
    }

    // epilogue2
    {
        float gpa[2] = {0.f, 0.f}, gpb[2] = {0.f, 0.f};
        #pragma unroll
        for (int mt = 0; mt < 2; mt++) {
            #pragma unroll
            for (int nt = 0; nt < 4; nt++) {
                int c0 = cb2 + 8 * nt + 2 * qc;
                float bb0 = sB2[c0], bb1 = sB2[c0 + 1];
                float w0 = sWg[c0], w1 = sWg[c0 + 1];
                float* d = acc2[mt][nt];
                d[0] = fmaxf(d[0] + bb0, 0.f);
                d[1] = fmaxf(d[1] + bb1, 0.f);
                d[2] = fmaxf(d[2] + bb0, 0.f);
                d[3] = fmaxf(d[3] + bb1, 0.f);
                gpa[mt] += d[0] * w0 + d[1] * w1;
                gpb[mt] += d[2] * w0 + d[3] * w1;
            }
        }
        #pragma unroll
        for (int mt = 0; mt < 2; mt++) {
            gpa[mt] += __shfl_xor_sync(0xffffffffu, gpa[mt], 1);
            gpa[mt] += __shfl_xor_sync(0xffffffffu, gpa[mt], 2);
            gpb[mt] += __shfl_xor_sync(0xffffffffu, gpb[mt], 1);
            gpb[mt] += __shfl_xor_sync(0xffffffffu, gpb[mt], 2);
        }
        if (qc == 0) {
            #pragma unroll
            for (int mt = 0; mt < 2; mt++) {
                sGate[wn2 * 64 + rb2 + 16 * mt + qr] = gpa[mt];
                sGate[wn2 * 64 + rb2 + 16 * mt + 8 + qr] = gpb[mt];
            }
        }
        __syncthreads();
        if (tid < 64 && tid < nE) {
            float lgv = sGate[tid] + sGate[64 + tid] + sGate[128 + tid] + sGate[192 + tid] + __ldg(bg);
            float ex = expf(lgv);
            atomicAdd(&g_denom[sR[tid]], ex);
            sGate[tid] = ex;
        }
        __syncthreads();
        #pragma unroll
        for (int mt = 0; mt < 2; mt++) {
            int ra = rb2 + 16 * mt + qr, rbr = ra + 8;
            if (ra < nE) {
                float exa = sGate[ra];
                float* base = g_aggr + (size_t)sR[ra] * MSG;
                #pragma unroll
                for (int nt = 0; nt < 4; nt++) {
                    int c0 = cb2 + 8 * nt + 2 * qc;
                    float* d = acc2[mt][nt];
                    red2(base + c0, exa * d[0], exa * d[1]);
                }
            }
            if (rbr < nE) {
                float exb = sGate[rbr];
                float* base = g_aggr + (size_t)sR[rbr] * MSG;
                #pragma unroll
                for (int nt = 0; nt < 4; nt++) {
                    int c0 = cb2 + 8 * nt + 2 * qc;
                    float* d = acc2[mt][nt];
                    red2(base + c0, exb * d[2], exb * d[3]);
                }
            }
        }
    }
}

// ---------------- agent MLP head: 3xTF32 mma (round-13 best) ----------------
#define SXQ_STR4  68
#define SHQ_STR4  132
#define AOFF_XH   0
#define AOFF_PART 135168
#define AOFF_INV  137216
#define AOFF_BH1  137472
#define AOFF_BH2  138496
#define AOFF_WO   139520
#define SMEM_AGM  140544

__global__ __launch_bounds__(256, 1) void k_agent_mma(
    const float* __restrict__ bh1, const float* __restrict__ bh2,
    const float* __restrict__ Wo,  const float* __restrict__ bo,
    float* __restrict__ out)
{
    extern __shared__ char smem[];
    float* sXf = (float*)(smem + AOFF_XH);
    float* sPart = (float*)(smem + AOFF_PART);
    float* sInv = (float*)(smem + AOFF_INV);
    float* sBH1 = (float*)(smem + AOFF_BH1);
    float* sBH2 = (float*)(smem + AOFF_BH2);
    float* sWo = (float*)(smem + AOFF_WO);

    int a0 = blockIdx.x * 64;
    int tid = threadIdx.x;
    int wid = tid >> 5, lane = tid & 31;
    int qr = lane >> 2, qc = lane & 3;

    if (tid < 64) {
        int a = a0 + tid;
        sInv[tid] = (a < N_AGENTS) ? 1.f / (g_denom[a] + 1e-9f) : 0.f;
    }
    sBH1[tid] = __ldg(bh1 + tid);
    sBH2[tid] = __ldg(bh2 + tid);
    sWo[tid] = __ldg(Wo + tid);
    __syncthreads();

    for (int i = tid; i < 64 * 32; i += 256) {
        int r = i >> 5, q = i & 31;
        int a = a0 + r;
        float4 v = (a < N_AGENTS) ? *((const float4*)g_aggr + (size_t)a * 32 + q)
                                  : make_float4(0.f, 0.f, 0.f, 0.f);
        float inv = sInv[r];
        float e[4] = {v.x * inv, v.y * inv, v.z * inv, v.w * inv};
        #pragma unroll
        for (int jj = 0; jj < 4; jj++) {
            int c = 4 * q + jj;
            int slot = 4 * (c >> 3) + (c & 3);
            int comp = (c >> 2) & 1;
            float hi = tf32r(e[jj]);
            float* fb = sXf + r * (4 * SXQ_STR4) + 4 * slot;
            fb[comp] = hi;
            fb[2 + comp] = tf32r(e[jj] - hi);
        }
    }
    __syncthreads();

    // GEMM1: 3xTF32
    float acc1[4][4][4];
    #pragma unroll
    for (int mt = 0; mt < 4; mt++)
        #pragma unroll
        for (int nt = 0; nt < 4; nt++)
            #pragma unroll
            for (int j = 0; j < 4; j++) acc1[mt][nt][j] = 0.f;

    {
        const float4* sXp = (const float4*)sXf;
        const float4* wf = g_Wh1q + (size_t)wid * 2048 + lane;
        float4 bcur[4], bnxt[4];
        #pragma unroll
        for (int nt = 0; nt < 4; nt++) bcur[nt] = __ldg(wf + nt * 32);

        for (int kg = 0; kg < 16; kg++) {
            if (kg + 1 < 16) {
                #pragma unroll
                for (int nt = 0; nt < 4; nt++) bnxt[nt] = __ldg(wf + (kg + 1) * 128 + nt * 32);
            }
            int aslot = 4 * kg + qc;
            uint32_t ah[4][4], al[4][4];
            #pragma unroll
            for (int mt = 0; mt < 4; mt++) {
                float4 a0v = sXp[(16 * mt + qr) * SXQ_STR4 + aslot];
                float4 a1v = sXp[(16 * mt + 8 + qr) * SXQ_STR4 + aslot];
                ah[mt][0] = __float_as_uint(a0v.x); ah[mt][1] = __float_as_uint(a1v.x);
                ah[mt][2] = __float_as_uint(a0v.y); ah[mt][3] = __float_as_uint(a1v.y);
                al[mt][0] = __float_as_uint(a0v.z); al[mt][1] = __float_as_uint(a1v.z);
                al[mt][2] = __float_as_uint(a0v.w); al[mt][3] = __float_as_uint(a1v.w);
            }
            #pragma unroll
            for (int nt = 0; nt < 4; nt++) {
                uint32_t bh[2] = {__float_as_uint(bcur[nt].x), __float_as_uint(bcur[nt].y)};
                uint32_t bl[2] = {__float_as_uint(bcur[nt].z), __float_as_uint(bcur[nt].w)};
                #pragma unroll
                for (int mt = 0; mt < 4; mt++) {
                    mma168(acc1[mt][nt], ah[mt], bh);
                    mma168(acc1[mt][nt], ah[mt], bl);
                    mma168(acc1[mt][nt], al[mt], bh);
                }
            }
            #pragma unroll
            for (int nt = 0; nt < 4; nt++) bcur[nt] = bnxt[nt];
        }
    }
    __syncthreads();

    // epilogue1
    int cb1 = 32 * wid;
    float* sHf = sXf;
    #pragma unroll
    for (int mt = 0; mt < 4; mt++) {
        int ra = 16 * mt + qr, rbr = ra + 8;
        #pragma unroll
        for (int nt = 0; nt < 4; nt++) {
            int c0 = cb1 + 8 * nt + 2 * qc;
            float bb0 = sBH1[c0], bb1 = sBH1[c0 + 1];
            float* d = acc1[mt][nt];
            #pragma unroll
            for (int u = 0; u < 2; u++) {
                int c = c0 + u;
                int slot = 4 * (c >> 3) + (c & 3);
                int comp = (c >> 2) & 1;
                float va = fmaxf(d[u] + (u ? bb1 : bb0), 0.f);
                float vb = fmaxf(d[2 + u] + (u ? bb1 : bb0), 0.f);
                float ha = tf32r(va), hb = tf32r(vb);
                float* fa = sHf + ra * (4 * SHQ_STR4) + 4 * slot;
                float* fb = sHf + rbr * (4 * SHQ_STR4) + 4 * slot;
                fa[comp] = ha; fa[2 + comp] = tf32r(va - ha);
                fb[comp] = hb; fb[2 + comp] = tf32r(vb - hb);
            }
        }
    }
    __syncthreads();

    // GEMM2: 3xTF32
    float acc2[4][4][4];
    #pragma unroll
    for (int mt = 0; mt < 4; mt++)
        #pragma unroll
        for (int nt = 0; nt < 4; nt++)
            #pragma unroll
            for (int j = 0; j < 4; j++) acc2[mt][nt][j] = 0.f;

    {
        const float4* sHp = (const float4*)sHf;
        const float4* wf = g_Wh2q + (size_t)wid * 4096 + lane;
        float4 bcur[4], bnxt[4];
        #pragma unroll
        for (int nt = 0; nt < 4; nt++) bcur[nt] = __ldg(wf + nt * 32);

        for (int kg = 0; kg < 32; kg++) {
            if (kg + 1 < 32) {
                #pragma unroll
                for (int nt = 0; nt < 4; nt++) bnxt[nt] = __ldg(wf + (kg + 1) * 128 + nt * 32);
            }
            int aslot = 4 * kg + qc;
            uint32_t ah[4][4], al[4][4];
            #pragma unroll
            for (int mt = 0; mt < 4; mt++) {
                float4 a0v = sHp[(16 * mt + qr) * SHQ_STR4 + aslot];
                float4 a1v = sHp[(16 * mt + 8 + qr) * SHQ_STR4 + aslot];
                ah[mt][0] = __float_as_uint(a0v.x); ah[mt][1] = __float_as_uint(a1v.x);
                ah[mt][2] = __float_as_uint(a0v.y); ah[mt][3] = __float_as_uint(a1v.y);
                al[mt][0] = __float_as_uint(a0v.z); al[mt][1] = __float_as_uint(a1v.z);
                al[mt][2] = __float_as_uint(a0v.w); al[mt][3] = __float_as_uint(a1v.w);
            }
            #pragma unroll
            for (int nt = 0; nt < 4; nt++) {
                uint32_t bh[2] = {__float_as_uint(bcur[nt].x), __float_as_uint(bcur[nt].y)};
                uint32_t bl[2] = {__float_as_uint(bcur[nt].z), __float_as_uint(bcur[nt].w)};
                #pragma unroll
                for (int mt = 0; mt < 4; mt++) {
                    mma168(acc2[mt][nt], ah[mt], bh);
                    mma168(acc2[mt][nt], ah[mt], bl);
                    mma168(acc2[mt][nt], al[mt], bh);
                }
            }
            #pragma unroll
            for (int nt = 0; nt < 4; nt++) bcur[nt] = bnxt[nt];
        }
    }

    // final epilogue
    {
        float pa[4] = {0.f, 0.f, 0.f, 0.f}, pb[4] = {0.f, 0.f, 0.f, 0.f};
        #pragma unroll
        for (int mt = 0; mt < 4; mt++) {
            #pragma unroll
            for (int nt = 0; nt < 4; nt++) {
                int c0 = cb1 + 8 * nt + 2 * qc;
                float bb0 = sBH2[c0], bb1 = sBH2[c0 + 1];
                float w0 = sWo[c0], w1 = sWo[c0 + 1];
                float* d = acc2[mt][nt];
                float m0 = fmaxf(d[0] + bb0, 0.f);
                float m1 = fmaxf(d[1] + bb1, 0.f);
                float m2 = fmaxf(d[2] + bb0, 0.f);
                float m3 = fmaxf(d[3] + bb1, 0.f);
                pa[mt] += m0 * w0 + m1 * w1;
                pb[mt] += m2 * w0 + m3 * w1;
            }
        }
        #pragma unroll
        for (int mt = 0; mt < 4; mt++) {
            pa[mt] += __shfl_xor_sync(0xffffffffu, pa[mt], 1);
            pa[mt] += __shfl_xor_sync(0xffffffffu, pa[mt], 2);
            pb[mt] += __shfl_xor_sync(0xffffffffu, pb[mt], 1);
            pb[mt] += __shfl_xor_sync(0xffffffffu, pb[mt], 2);
        }
        if (qc == 0) {
            #pragma unroll
            for (int mt = 0; mt < 4; mt++) {
                sPart[wid * 64 + 16 * mt + qr] = pa[mt];
                sPart[wid * 64 + 16 * mt + 8 + qr] = pb[mt];
            }
        }
        __syncthreads();
        if (tid < 64) {
            int a = a0 + tid;
            if (a < N_AGENTS) {
                float s = __ldg(bo);
                #pragma unroll
                for (int w = 0; w < 8; w++) s += sPart[w * 64 + tid];
                out[a] = tanhf(s);
            }
        }
    }
}

// ---------------- launch ----------------
extern "C" void kernel_launch(void* const* d_in, const int* in_sizes, int n_in,
                              void* d_out, int out_size)
{
    const float* node = (const float*)d_in[0];
    const float* ef   = (const float*)d_in[1];
    const float* W1   = (const float*)d_in[2];
    const float* b1   = (const float*)d_in[3];
    const float* W2   = (const float*)d_in[4];
    const float* b2   = (const float*)d_in[5];
    const float* wg   = (const float*)d_in[6];
    const float* bg   = (const float*)d_in[7];
    const float* Wh1  = (const float*)d_in[8];
    const float* bh1  = (const float*)d_in[9];
    const float* Wh2  = (const float*)d_in[10];
    const float* bh2  = (const float*)d_in[11];
    const float* Wo   = (const float*)d_in[12];
    const float* bo   = (const float*)d_in[13];
    const int*   snd  = (const int*)d_in[14];
    const int*   rcv  = (const int*)d_in[15];
    float* out = (float*)d_out;

    cudaFuncSetAttribute(k_edge_mma,  cudaFuncAttributeMaxDynamicSharedMemorySize, SMEM_EDGE);
    cudaFuncSetAttribute(k_agent_mma, cudaFuncAttributeMaxDynamicSharedMemorySize, SMEM_AGM);

    k_zero<<<1, 32>>>();
    k_setup<<<(N_EDGESC + 255) / 256, 256>>>(rcv, W1, W2, Wh1, Wh2);
    k_edge_mma<<<(N_EDGESC + 63) / 64, 256, SMEM_EDGE>>>(node, ef, b1, b2, wg, bg, snd, rcv);
    k_agent_mma<<<(N_AGENTS + 63) / 64, 256, SMEM_AGM>>>(bh1, bh2, Wo, bo, out);
}

// round 16
// speedup vs baseline: 1.0929x; 1.0582x over previous
#include <cuda_runtime.h>
#include <math.h>
#include <stdint.h>

#define N_NODES  50000
#define N_EDGESC 800000
#define ND       64
#define ED       32
#define MSG      128
#define HID      256
#define N_AGENTS 25000

// ---------------- scratch ----------------
__device__ int          g_eidx[N_EDGESC];
__device__ int          g_cnt;
__device__ float        g_denom[N_AGENTS];
__device__ float        g_aggr[(size_t)N_AGENTS * MSG];
// edge weights: fragment-major tf32 float2 (hi only)
__device__ __align__(16) float2 g_W1f[8 * 20 * 4 * 32];
__device__ __align__(16) float2 g_W2f[4 * 32 * 4 * 32];
// agent weights: fragment-major float4 = (hi_k, hi_k4, lo_k, lo_k4)  [3xTF32]
__device__ __align__(16) float4 g_Wh1q[8 * 16 * 4 * 32];
__device__ __align__(16) float4 g_Wh2q[8 * 32 * 4 * 32];

__device__ __forceinline__ float tf32r(float x) {
    uint32_t u;
    asm("cvt.rna.tf32.f32 %0, %1;" : "=r"(u) : "f"(x));
    return __uint_as_float(u);
}
__device__ __forceinline__ void mma168(float* d, const uint32_t* a, const uint32_t* b) {
    asm volatile(
        "mma.sync.aligned.m16n8k8.row.col.f32.tf32.tf32.f32 "
        "{%0,%1,%2,%3}, {%4,%5,%6,%7}, {%8,%9}, {%0,%1,%2,%3};"
        : "+f"(d[0]), "+f"(d[1]), "+f"(d[2]), "+f"(d[3])
        : "r"(a[0]), "r"(a[1]), "r"(a[2]), "r"(a[3]), "r"(b[0]), "r"(b[1]));
}
__device__ __forceinline__ void red2(float* dst, float x, float y) {
    asm volatile("red.global.add.v2.f32 [%0], {%1,%2};" :: "l"(dst), "f"(x), "f"(y) : "memory");
}

// ---------------- tiny counter reset (must precede k_setup) ----------------
__global__ void k_zero() { if (threadIdx.x == 0) g_cnt = 0; }

// ---------------- fused setup: aggr/denom zero + edge compact + weight prep ----------------
__global__ void k_setup(const int* __restrict__ rcv,
                        const float* __restrict__ W1, const float* __restrict__ W2,
                        const float* __restrict__ Wh1, const float* __restrict__ Wh2) {
    int i = blockIdx.x * blockDim.x + threadIdx.x;
    if (i < N_AGENTS * MSG / 4)
        ((float4*)g_aggr)[i] = make_float4(0.f, 0.f, 0.f, 0.f);
    if (i < N_AGENTS) g_denom[i] = 0.f;
    if (i < N_EDGESC && rcv[i] < N_AGENTS) {     // g_cnt zeroed by preceding k_zero launch
        int p = atomicAdd(&g_cnt, 1);
        g_eidx[p] = i;
    }
    if (i < 20480) {                               // W1f
        int lane = i & 31, nt = (i >> 5) & 3, kg = (i >> 7) % 20, wn = i / 2560;
        int qr = lane >> 2, qc = lane & 3;
        int n = 32 * wn + 8 * nt + qr;
        int k0 = 8 * kg + qc;
        g_W1f[i] = make_float2(tf32r(W1[(size_t)k0 * HID + n]),
                               tf32r(W1[(size_t)(k0 + 4) * HID + n]));
    }
    int j = i - 20480;
    if (j >= 0 && j < 16384) {                     // W2f
        int lane = j & 31, nt = (j >> 5) & 3, kg = (j >> 7) & 31, wn = j >> 12;
        int qr = lane >> 2, qc = lane & 3;
        int n = 32 * wn + 8 * nt + qr;
        int k0 = 8 * kg + qc;
        g_W2f[j] = make_float2(tf32r(W2[(size_t)k0 * MSG + n]),
                               tf32r(W2[(size_t)(k0 + 4) * MSG + n]));
    }
    int t = i - 36864;
    if (t >= 0 && t < 16384) {                     // Wh1q hi/lo
        int lane = t & 31, nt = (t >> 5) & 3, kg = (t >> 7) & 15, wn = t >> 11;
        int qr = lane >> 2, qc = lane & 3;
        int n = 32 * wn + 8 * nt + qr;
        int k0 = 8 * kg + qc;
        float w0 = Wh1[(size_t)k0 * HID + n], w1 = Wh1[(size_t)(k0 + 4) * HID + n];
        float h0 = tf32r(w0), h1 = tf32r(w1);
        g_Wh1q[t] = make_float4(h0, h1, tf32r(w0 - h0), tf32r(w1 - h1));
    }
    int u = i - 53248;
    if (u >= 0 && u < 32768) {                     // Wh2q hi/lo
        int lane = u & 31, nt = (u >> 5) & 3, kg = (u >> 7) & 31, wn = u >> 12;
        int qr = lane >> 2, qc = lane & 3;
        int n = 32 * wn + 8 * nt + qr;
        int k0 = 8 * kg + qc;
        float w0 = Wh2[(size_t)k0 * HID + n], w1 = Wh2[(size_t)(k0 + 4) * HID + n];
        float h0 = tf32r(w0), h1 = tf32r(w1);
        g_Wh2q[u] = make_float4(h0, h1, tf32r(w0 - h0), tf32r(w1 - h1));
    }
}

// ---------------- fused edge MLP + softmax-numerator scatter (converged best) ----------------
#define SA_STR2  84
#define SH_STR2  132
#define OFF_AH   0
#define OFF_EG   67584
#define OFF_S    67840
#define OFF_R    68096
#define OFF_B1   68352
#define OFF_B2   69376
#define OFF_WG   69888
#define OFF_GATE 70400
#define SMEM_EDGE 71424

__global__ __launch_bounds__(256, 2) void k_edge_mma(
    const float* __restrict__ nf, const float* __restrict__ ef,
    const float* __restrict__ b1, const float* __restrict__ b2,
    const float* __restrict__ wg, const float* __restrict__ bg,
    const int* __restrict__ snd, const int* __restrict__ rcv)
{
    extern __shared__ char smem[];
    float* sAf = (float*)(smem + OFF_AH);
    int*   sEg = (int*)(smem + OFF_EG);
    int*   sS  = (int*)(smem + OFF_S);
    int*   sR  = (int*)(smem + OFF_R);
    float* sB1 = (float*)(smem + OFF_B1);
    float* sB2 = (float*)(smem + OFF_B2);
    float* sWg = (float*)(smem + OFF_WG);
    float* sGate = (float*)(smem + OFF_GATE);

    int cnt = g_cnt;
    int ci0 = blockIdx.x * 64;
    if (ci0 >= cnt) return;
    int nE = min(64, cnt - ci0);

    int tid = threadIdx.x;
    int wid = tid >> 5, lane = tid & 31;
    int qr = lane >> 2, qc = lane & 3;

    if (tid < 64) {
        int e = (tid < nE) ? g_eidx[ci0 + tid] : g_eidx[ci0];
        sEg[tid] = e;
        sS[tid] = snd[e];
        sR[tid] = rcv[e];
    }
    sB1[tid] = __ldg(b1 + tid);
    if (tid < 128) { sB2[tid] = __ldg(b2 + tid); sWg[tid] = __ldg(wg + tid); }
    __syncthreads();

    for (int i = tid; i < 64 * 40; i += 256) {
        int r = i / 40, q = i % 40;
        float4 v;
        int cb;
        if (q < 16)      { v = __ldg((const float4*)(nf + (size_t)sS[r] * ND) + q);         cb = 4 * q; }
        else if (q < 32) { v = __ldg((const float4*)(nf + (size_t)sR[r] * ND) + (q - 16));  cb = 64 + 4 * (q - 16); }
        else             { v = __ldg((const float4*)(ef + (size_t)sEg[r] * ED) + (q - 32)); cb = 128 + 4 * (q - 32); }
        int g = cb >> 3, comp = (cb >> 2) & 1;
        float* p = sAf + r * (2 * SA_STR2) + 8 * g + comp;
        p[0] = tf32r(v.x); p[2] = tf32r(v.y); p[4] = tf32r(v.z); p[6] = tf32r(v.w);
    }
    __syncthreads();

    // GEMM1: 64x256, K=160
    float acc1[4][4][4];
    #pragma unroll
    for (int mt = 0; mt < 4; mt++)
        #pragma unroll
        for (int nt = 0; nt < 4; nt++)
            #pragma unroll
            for (int j = 0; j < 4; j++) acc1[mt][nt][j] = 0.f;

    {
        const float2* sAp = (const float2*)sAf;
        const float2* wf = g_W1f + (size_t)wid * 2560 + lane;
        float2 bcur[4], bnxt[4];
        #pragma unroll
        for (int nt = 0; nt < 4; nt++) bcur[nt] = __ldg(wf + nt * 32);

        for (int kg = 0; kg < 20; kg++) {
            if (kg + 1 < 20) {
                #pragma unroll
                for (int nt = 0; nt < 4; nt++) bnxt[nt] = __ldg(wf + (kg + 1) * 128 + nt * 32);
            }
            int aslot = 4 * kg + qc;
            uint32_t af[4][4];
            #pragma unroll
            for (int mt = 0; mt < 4; mt++) {
                float2 a0 = sAp[(16 * mt + qr) * SA_STR2 + aslot];
                float2 a1 = sAp[(16 * mt + 8 + qr) * SA_STR2 + aslot];
                af[mt][0] = __float_as_uint(a0.x); af[mt][1] = __float_as_uint(a1.x);
                af[mt][2] = __float_as_uint(a0.y); af[mt][3] = __float_as_uint(a1.y);
            }
            uint32_t bf[4][2];
            #pragma unroll
            for (int nt = 0; nt < 4; nt++) {
                bf[nt][0] = __float_as_uint(bcur[nt].x);
                bf[nt][1] = __float_as_uint(bcur[nt].y);
            }
            #pragma unroll
            for (int mt = 0; mt < 4; mt++)
                #pragma unroll
                for (int nt = 0; nt < 4; nt++)
                    mma168(acc1[mt][nt], af[mt], bf[nt]);
            #pragma unroll
            for (int nt = 0; nt < 4; nt++) bcur[nt] = bnxt[nt];
        }
    }
    __syncthreads();

    // epilogue1
    int cb1 = 32 * wid;
    float* sHf = sAf;
    #pragma unroll
    for (int mt = 0; mt < 4; mt++) {
        int ra = 16 * mt + qr, rbr = ra + 8;
        #pragma unroll
        for (int nt = 0; nt < 4; nt++) {
            int c0 = cb1 + 8 * nt + 2 * qc;
            float bb0 = sB1[c0], bb1 = sB1[c0 + 1];
            float* d = acc1[mt][nt];
            #pragma unroll
            for (int u = 0; u < 2; u++) {
                int c = c0 + u;
                int g = c >> 3, e = c & 7;
                int idx = 8 * g + 2 * (e & 3) + (e >> 2);
                sHf[ra * (2 * SH_STR2) + idx]  = tf32r(fmaxf(d[u] + (u ? bb1 : bb0), 0.f));
                sHf[rbr * (2 * SH_STR2) + idx] = tf32r(fmaxf(d[2 + u] + (u ? bb1 : bb0), 0.f));
            }
        }
    }
    __syncthreads();

    // GEMM2: 64x128, K=256
    int wm2 = wid & 1, wn2 = wid >> 1;
    int rb2 = 32 * wm2, cb2 = 32 * wn2;

    float acc2[2][4][4];
    #pragma unroll
    for (int mt = 0; mt < 2; mt++)
        #pragma unroll
        for (int nt = 0; nt < 4; nt++)
            #pragma unroll
            for (int j = 0; j < 4; j++) acc2[mt][nt][j] = 0.f;

    {
        const float2* sHp = (const float2*)sHf;
        const float2* wf = g_W2f + (size_t)wn2 * 4096 + lane;
        float2 bcur[4], bnxt[4];
        #pragma unroll
        for (int nt = 0; nt < 4; nt++) bcur[nt] = __ldg(wf + nt * 32);

        for (int kg = 0; kg < 32; kg++) {
            if (kg + 1 < 32) {
                #pragma unroll
                for (int nt = 0; nt < 4; nt++) bnxt[nt] = __ldg(wf + (kg + 1) * 128 + nt * 32);
            }
            int aslot = 4 * kg + qc;
            uint32_t af[2][4];
            #pragma unroll
            for (int mt = 0; mt < 2; mt++) {
                float2 a0 = sHp[(rb2 + 16 * mt + qr) * SH_STR2 + aslot];
                float2 a1 = sHp[(rb2 + 16 * mt + 8 + qr) * SH_STR2 + aslot];
                af[mt][0] = __float_as_uint(a0.x); af[mt][1] = __float_as_uint(a1.x);
                af[mt][2] = __float_as_uint(a0.y); af[mt][3] = __float_as_uint(a1.y);
            }
            uint32_t bf[4][2];
            #pragma unroll
            for (int nt = 0; nt < 4; nt++) {
                bf[nt][0] = __float_as_uint(bcur[nt].x);
                bf[nt][1] = __float_as_uint(bcur[nt].y);
            }
            #pragma unroll
            for (int mt = 0; mt < 2; mt++)
                #pragma unroll
                for (int nt = 0; nt < 4; nt++)
                    mma168(acc2[mt][nt], af[mt], bf[nt]);
            #pragma unroll
            for (int nt = 0; nt < 4; nt++) bcur[nt] = bnxt[nt];
        }
    }

    // epilogue2
    {
        float gpa[2] = {0.f, 0.f}, gpb[2] = {0.f, 0.f};
        #pragma unroll
        for (int mt = 0; mt < 2; mt++) {
            #pragma unroll
            for (int nt = 0; nt < 4; nt++) {
                int c0 = cb2 + 8 * nt + 2 * qc;
                float bb0 = sB2[c0], bb1 = sB2[c0 + 1];
                float w0 = sWg[c0], w1 = sWg[c0 + 1];
                float* d = acc2[mt][nt];
                d[0] = fmaxf(d[0] + bb0, 0.f);
                d[1] = fmaxf(d[1] + bb1, 0.f);
                d[2] = fmaxf(d[2] + bb0, 0.f);
                d[3] = fmaxf(d[3] + bb1, 0.f);
                gpa[mt] += d[0] * w0 + d[1] * w1;
                gpb[mt] += d[2] * w0 + d[3] * w1;
            }
        }
        #pragma unroll
        for (int mt = 0; mt < 2; mt++) {
            gpa[mt] += __shfl_xor_sync(0xffffffffu, gpa[mt], 1);
            gpa[mt] += __shfl_xor_sync(0xffffffffu, gpa[mt], 2);
            gpb[mt] += __shfl_xor_sync(0xffffffffu, gpb[mt], 1);
            gpb[mt] += __shfl_xor_sync(0xffffffffu, gpb[mt], 2);
        }
        if (qc == 0) {
            #pragma unroll
            for (int mt = 0; mt < 2; mt++) {
                sGate[wn2 * 64 + rb2 + 16 * mt + qr] = gpa[mt];
                sGate[wn2 * 64 + rb2 + 16 * mt + 8 + qr] = gpb[mt];
            }
        }
        __syncthreads();
        if (tid < 64 && tid < nE) {
            float lgv = sGate[tid] + sGate[64 + tid] + sGate[128 + tid] + sGate[192 + tid] + __ldg(bg);
            float ex = expf(lgv);
            atomicAdd(&g_denom[sR[tid]], ex);
            sGate[tid] = ex;
        }
        __syncthreads();
        #pragma unroll
        for (int mt = 0; mt < 2; mt++) {
            int ra = rb2 + 16 * mt + qr, rbr = ra + 8;
            if (ra < nE) {
                float exa = sGate[ra];
                float* base = g_aggr + (size_t)sR[ra] * MSG;
                #pragma unroll
                for (int nt = 0; nt < 4; nt++) {
                    int c0 = cb2 + 8 * nt + 2 * qc;
                    float* d = acc2[mt][nt];
                    red2(base + c0, exa * d[0], exa * d[1]);
                }
            }
            if (rbr < nE) {
                float exb = sGate[rbr];
                float* base = g_aggr + (size_t)sR[rbr] * MSG;
                #pragma unroll
                for (int nt = 0; nt < 4; nt++) {
                    int c0 = cb2 + 8 * nt + 2 * qc;
                    float* d = acc2[mt][nt];
                    red2(base + c0, exb * d[2], exb * d[3]);
                }
            }
        }
    }
}

// ---------------- agent MLP head: 3xTF32 mma, fp32 smem + on-the-fly hi/lo split ----------------
// activations stored as plain fp32 in pair layout; hi/lo computed at fragment load.
// smem 73KB -> 2 CTAs/SM; regs capped 128 via launch_bounds.
#define AX_STR2   68            // X pair row stride (float2); 544 B (mod 128 = 32)
#define AH_STR2   132           // H pair row stride (float2); 1056 B (mod 128 = 32)
#define AOFF_XH   0             // union: sX 34816 / sH 67584
#define AOFF_PART 67584         // 8 x 64 f = 2048
#define AOFF_INV  69632         // 64 f
#define AOFF_BH1  69888         // 256 f
#define AOFF_BH2  70912         // 256 f
#define AOFF_WO   71936         // 256 f
#define SMEM_AGM  72960

__global__ __launch_bounds__(256, 2) void k_agent_mma(
    const float* __restrict__ bh1, const float* __restrict__ bh2,
    const float* __restrict__ Wo,  const float* __restrict__ bo,
    float* __restrict__ out)
{
    extern __shared__ char smem[];
    float* sXf = (float*)(smem + AOFF_XH);
    float* sPart = (float*)(smem + AOFF_PART);
    float* sInv = (float*)(smem + AOFF_INV);
    float* sBH1 = (float*)(smem + AOFF_BH1);
    float* sBH2 = (float*)(smem + AOFF_BH2);
    float* sWo = (float*)(smem + AOFF_WO);

    int a0 = blockIdx.x * 64;
    int tid = threadIdx.x;
    int wid = tid >> 5, lane = tid & 31;
    int qr = lane >> 2, qc = lane & 3;

    if (tid < 64) {
        int a = a0 + tid;
        sInv[tid] = (a < N_AGENTS) ? 1.f / (g_denom[a] + 1e-9f) : 0.f;
    }
    sBH1[tid] = __ldg(bh1 + tid);
    sBH2[tid] = __ldg(bh2 + tid);
    sWo[tid] = __ldg(Wo + tid);
    __syncthreads();

    // load x = aggr * inv (plain fp32, pair layout)
    for (int i = tid; i < 64 * 32; i += 256) {
        int r = i >> 5, q = i & 31;
        int a = a0 + r;
        float4 v = (a < N_AGENTS) ? *((const float4*)g_aggr + (size_t)a * 32 + q)
                                  : make_float4(0.f, 0.f, 0.f, 0.f);
        float inv = sInv[r];
        float e[4] = {v.x * inv, v.y * inv, v.z * inv, v.w * inv};
        #pragma unroll
        for (int jj = 0; jj < 4; jj++) {
            int c = 4 * q + jj;
            int slot = 4 * (c >> 3) + (c & 3);
            int comp = (c >> 2) & 1;
            sXf[r * (2 * AX_STR2) + 2 * slot + comp] = e[jj];
        }
    }
    __syncthreads();

    // GEMM1: h1(64x256) = relu(x(64x128) @ Wh1 + bh1). 1x8 warp grid, 3xTF32 on-the-fly.
    float acc1[4][4][4];
    #pragma unroll
    for (int mt = 0; mt < 4; mt++)
        #pragma unroll
        for (int nt = 0; nt < 4; nt++)
            #pragma unroll
            for (int j = 0; j < 4; j++) acc1[mt][nt][j] = 0.f;

    {
        const float2* sXp = (const float2*)sXf;
        const float4* wf = g_Wh1q + (size_t)wid * 2048 + lane;

        for (int kg = 0; kg < 16; kg++) {
            int aslot = 4 * kg + qc;
            uint32_t ah[4][4], al[4][4];
            #pragma unroll
            for (int mt = 0; mt < 4; mt++) {
                float2 a0v = sXp[(16 * mt + qr) * AX_STR2 + aslot];
                float2 a1v = sXp[(16 * mt + 8 + qr) * AX_STR2 + aslot];
                float h;
                h = tf32r(a0v.x); ah[mt][0] = __float_as_uint(h); al[mt][0] = __float_as_uint(tf32r(a0v.x - h));
                h = tf32r(a1v.x); ah[mt][1] = __float_as_uint(h); al[mt][1] = __float_as_uint(tf32r(a1v.x - h));
                h = tf32r(a0v.y); ah[mt][2] = __float_as_uint(h); al[mt][2] = __float_as_uint(tf32r(a0v.y - h));
                h = tf32r(a1v.y); ah[mt][3] = __float_as_uint(h); al[mt][3] = __float_as_uint(tf32r(a1v.y - h));
            }
            #pragma unroll
            for (int nt = 0; nt < 4; nt++) {
                float4 b = __ldg(wf + kg * 128 + nt * 32);
                uint32_t bh[2] = {__float_as_uint(b.x), __float_as_uint(b.y)};
                uint32_t bl[2] = {__float_as_uint(b.z), __float_as_uint(b.w)};
                #pragma unroll
                for (int mt = 0; mt < 4; mt++) {
                    mma168(acc1[mt][nt], ah[mt], bh);
                    mma168(acc1[mt][nt], ah[mt], bl);
                    mma168(acc1[mt][nt], al[mt], bh);
                }
            }
        }
    }
    __syncthreads();

    // epilogue1: h1 = relu(acc + bh1) stored as plain fp32 (pair layout)
    int cb1 = 32 * wid;
    float* sHf = sXf;
    #pragma unroll
    for (int mt = 0; mt < 4; mt++) {
        int ra = 16 * mt + qr, rbr = ra + 8;
        #pragma unroll
        for (int nt = 0; nt < 4; nt++) {
            int c0 = cb1 + 8 * nt + 2 * qc;
            float bb0 = sBH1[c0], bb1 = sBH1[c0 + 1];
            float* d = acc1[mt][nt];
            #pragma unroll
            for (int u = 0; u < 2; u++) {
                int c = c0 + u;
                int slot = 4 * (c >> 3) + (c & 3);
                int comp = (c >> 2) & 1;
                sHf[ra * (2 * AH_STR2) + 2 * slot + comp]  = fmaxf(d[u] + (u ? bb1 : bb0), 0.f);
                sHf[rbr * (2 * AH_STR2) + 2 * slot + comp] = fmaxf(d[2 + u] + (u ? bb1 : bb0), 0.f);
            }
        }
    }
    __syncthreads();

    // GEMM2: h2(64x256) = h1(64x256) @ Wh2. 1x8 warp grid, K=256, 3xTF32 on-the-fly.
    float acc2[4][4][4];
    #pragma unroll
    for (int mt = 0; mt < 4; mt++)
        #pragma unroll
        for (int nt = 0; nt < 4; nt++)
            #pragma unroll
            for (int j = 0; j < 4; j++) acc2[mt][nt][j] = 0.f;

    {
        const float2* sHp = (const float2*)sHf;
        const float4* wf = g_Wh2q + (size_t)wid * 4096 + lane;

        for (int kg = 0; kg < 32; kg++) {
            int aslot = 4 * kg + qc;
            uint32_t ah[4][4], al[4][4];
            #pragma unroll
            for (int mt = 0; mt < 4; mt++) {
                float2 a0v = sHp[(16 * mt + qr) * AH_STR2 + aslot];
                float2 a1v = sHp[(16 * mt + 8 + qr) * AH_STR2 + aslot];
                float h;
                h = tf32r(a0v.x); ah[mt][0] = __float_as_uint(h); al[mt][0] = __float_as_uint(tf32r(a0v.x - h));
                h = tf32r(a1v.x); ah[mt][1] = __float_as_uint(h); al[mt][1] = __float_as_uint(tf32r(a1v.x - h));
                h = tf32r(a0v.y); ah[mt][2] = __float_as_uint(h); al[mt][2] = __float_as_uint(tf32r(a0v.y - h));
                h = tf32r(a1v.y); ah[mt][3] = __float_as_uint(h); al[mt][3] = __float_as_uint(tf32r(a1v.y - h));
            }
            #pragma unroll
            for (int nt = 0; nt < 4; nt++) {
                float4 b = __ldg(wf + kg * 128 + nt * 32);
                uint32_t bh[2] = {__float_as_uint(b.x), __float_as_uint(b.y)};
                uint32_t bl[2] = {__float_as_uint(b.z), __float_as_uint(b.w)};
                #pragma unroll
                for (int mt = 0; mt < 4; mt++) {
                    mma168(acc2[mt][nt], ah[mt], bh);
                    mma168(acc2[mt][nt], ah[mt], bl);
                    mma168(acc2[mt][nt], al[mt], bh);
                }
            }
        }
    }

    // final epilogue: h2 = relu(acc2 + bh2); Wo dot partials; reduce; tanh
    {
        float pa[4] = {0.f, 0.f, 0.f, 0.f}, pb[4] = {0.f, 0.f, 0.f, 0.f};
        #pragma unroll
        for (int mt = 0; mt < 4; mt++) {
            #pragma unroll
            for (int nt = 0; nt < 4; nt++) {
                int c0 = cb1 + 8 * nt + 2 * qc;
                float bb0 = sBH2[c0], bb1 = sBH2[c0 + 1];
                float w0 = sWo[c0], w1 = sWo[c0 + 1];
                float* d = acc2[mt][nt];
                float m0 = fmaxf(d[0] + bb0, 0.f);
                float m1 = fmaxf(d[1] + bb1, 0.f);
                float m2 = fmaxf(d[2] + bb0, 0.f);
                float m3 = fmaxf(d[3] + bb1, 0.f);
                pa[mt] += m0 * w0 + m1 * w1;
                pb[mt] += m2 * w0 + m3 * w1;
            }
        }
        #pragma unroll
        for (int mt = 0; mt < 4; mt++) {
            pa[mt] += __shfl_xor_sync(0xffffffffu, pa[mt], 1);
            pa[mt] += __shfl_xor_sync(0xffffffffu, pa[mt], 2);
            pb[mt] += __shfl_xor_sync(0xffffffffu, pb[mt], 1);
            pb[mt] += __shfl_xor_sync(0xffffffffu, pb[mt], 2);
        }
        if (qc == 0) {
            #pragma unroll
            for (int mt = 0; mt < 4; mt++) {
                sPart[wid * 64 + 16 * mt + qr] = pa[mt];
                sPart[wid * 64 + 16 * mt + 8 + qr] = pb[mt];
            }
        }
        __syncthreads();
        if (tid < 64) {
            int a = a0 + tid;
            if (a < N_AGENTS) {
                float s = __ldg(bo);
                #pragma unroll
                for (int w = 0; w < 8; w++) s += sPart[w * 64 + tid];
                out[a] = tanhf(s);
            }
        }
    }
}

// ---------------- launch ----------------
extern "C" void kernel_launch(void* const* d_in, const int* in_sizes, int n_in,
                              void* d_out, int out_size)
{
    const float* node = (const float*)d_in[0];
    const float* ef   = (const float*)d_in[1];
    const float* W1   = (const float*)d_in[2];
    const float* b1   = (const float*)d_in[3];
    const float* W2   = (const float*)d_in[4];
    const float* b2   = (const float*)d_in[5];
    const float* wg   = (const float*)d_in[6];
    const float* bg   = (const float*)d_in[7];
    const float* Wh1  = (const float*)d_in[8];
    const float* bh1  = (const float*)d_in[9];
    const float* Wh2  = (const float*)d_in[10];
    const float* bh2  = (const float*)d_in[11];
    const float* Wo   = (const float*)d_in[12];
    const float* bo   = (const float*)d_in[13];
    const int*   snd  = (const int*)d_in[14];
    const int*   rcv  = (const int*)d_in[15];
    float* out = (float*)d_out;

    cudaFuncSetAttribute(k_edge_mma,  cudaFuncAttributeMaxDynamicSharedMemorySize, SMEM_EDGE);
    cudaFuncSetAttribute(k_agent_mma, cudaFuncAttributeMaxDynamicSharedMemorySize, SMEM_AGM);

    k_zero<<<1, 32>>>();
    k_setup<<<(N_EDGESC + 255) / 256, 256>>>(rcv, W1, W2, Wh1, Wh2);
    k_edge_mma<<<(N_EDGESC + 63) / 64, 256, SMEM_EDGE>>>(node, ef, b1, b2, wg, bg, snd, rcv);
    k_agent_mma<<<(N_AGENTS + 63) / 64, 256, SMEM_AGM>>>(bh1, bh2, Wo, bo, out);
}